// round 1
// baseline (speedup 1.0000x reference)
#include <cuda_runtime.h>
#include <cuda_bf16.h>
#include <math.h>

// Problem constants
#define BB 4
#define TT 2048
#define EE 1024
#define HH 16
#define DD 64
#define MM (BB*TT)        // 8192
#define FF (4*EE)         // 4096

// ---------------- scratch (device globals; no allocation allowed) -------------
__device__ float g_x [MM*EE];   // x after embed (residual 1 input)
__device__ float g_h [MM*EE];   // LN output (reused for ln1 and ln2)
__device__ float g_q [MM*EE];   // q, layout [B,T,H,D] == [M,E]
__device__ float g_k [MM*EE];
__device__ float g_v [MM*EE];
__device__ float g_o [MM*EE];   // attention output, concat heads [B,T,E]
__device__ float g_x2[MM*EE];   // x + attn_proj (residual 2 input)
__device__ float g_m [MM*FF];   // gelu(fc) activations

// ---------------- embed: x = wte[ids] + wpe ----------------------------------
__global__ __launch_bounds__(256) void embed_kernel(
    const int* __restrict__ ids, const float* __restrict__ wte,
    const float* __restrict__ wpe, float* __restrict__ X)
{
    int i = blockIdx.x * 256 + threadIdx.x;    // float4 index over M*E/4
    int row = i >> 8;                           // 256 float4 per row
    int c   = i & 255;
    int t   = row & (TT - 1);
    int id  = ids[row];
    float4 a = ((const float4*)wte)[(size_t)id * 256 + c];
    float4 p = ((const float4*)wpe)[(size_t)t  * 256 + c];
    a.x += p.x; a.y += p.y; a.z += p.z; a.w += p.w;
    ((float4*)X)[i] = a;
}

// ---------------- layernorm (one block per row, E=1024) -----------------------
__global__ __launch_bounds__(256) void ln_kernel(
    const float* __restrict__ X, const float* __restrict__ G,
    const float* __restrict__ Bt, float* __restrict__ Y)
{
    __shared__ float red[16];
    int row = blockIdx.x, tid = threadIdx.x;
    const float4* x4 = (const float4*)(X + ((size_t)row << 10));
    float4 a = x4[tid];
    float s  = a.x + a.y + a.z + a.w;
    float sq = a.x*a.x + a.y*a.y + a.z*a.z + a.w*a.w;
    #pragma unroll
    for (int o = 16; o; o >>= 1) {
        s  += __shfl_xor_sync(0xffffffffu, s,  o);
        sq += __shfl_xor_sync(0xffffffffu, sq, o);
    }
    if ((tid & 31) == 0) { red[tid >> 5] = s; red[8 + (tid >> 5)] = sq; }
    __syncthreads();
    float ts = 0.f, tq = 0.f;
    #pragma unroll
    for (int i = 0; i < 8; i++) { ts += red[i]; tq += red[8 + i]; }
    float mean = ts * (1.f / 1024.f);
    float var  = tq * (1.f / 1024.f) - mean * mean;
    float inv  = rsqrtf(var + 1e-5f);
    float4 g4 = ((const float4*)G)[tid];
    float4 b4 = ((const float4*)Bt)[tid];
    float4 o;
    o.x = (a.x - mean) * inv * g4.x + b4.x;
    o.y = (a.y - mean) * inv * g4.y + b4.y;
    o.z = (a.z - mean) * inv * g4.z + b4.z;
    o.w = (a.w - mean) * inv * g4.w + b4.w;
    ((float4*)(Y + ((size_t)row << 10)))[tid] = o;
}

// ---------------- tiled SGEMM: C = act(A@W + bias [+ R]) ----------------------
// WL=0: W row-major [K,N].  WL=1: W is (H,E,D): idx = (n/64)*K*64 + k*64 + n%64
template<int WL, bool GELU_, bool RES>
__global__ __launch_bounds__(256) void gemm_kernel(
    const float* __restrict__ A, const float* __restrict__ W,
    const float* __restrict__ bias, const float* __restrict__ Rp,
    float* __restrict__ C, int M, int N, int K)
{
    __shared__ float As[16][128];
    __shared__ float Ws[16][128];
    int tid = threadIdx.x;
    int bn = blockIdx.x * 128, bm = blockIdx.y * 128;
    int tx = tid & 15, ty = tid >> 4;
    float acc[8][8];
    #pragma unroll
    for (int i = 0; i < 8; i++)
        #pragma unroll
        for (int j = 0; j < 8; j++) acc[i][j] = 0.f;

    int arow = tid >> 2;          // 0..63 (two passes: +64)
    int akc  = (tid & 3) << 2;    // k offset 0,4,8,12
    int wcol = (tid & 31) << 2;   // 0..124
    int wrow = tid >> 5;          // 0..7 (two passes: +8)

    for (int k0 = 0; k0 < K; k0 += 16) {
        #pragma unroll
        for (int p = 0; p < 2; p++) {
            int mm = arow + p * 64;
            float4 va = *(const float4*)(A + (size_t)(bm + mm) * K + k0 + akc);
            As[akc + 0][mm] = va.x; As[akc + 1][mm] = va.y;
            As[akc + 2][mm] = va.z; As[akc + 3][mm] = va.w;
        }
        #pragma unroll
        for (int p = 0; p < 2; p++) {
            int kk = wrow + p * 8;
            int n  = bn + wcol;
            const float* wp;
            if (WL == 0) wp = W + (size_t)(k0 + kk) * N + n;
            else         wp = W + ((size_t)(n >> 6)) * (size_t)K * 64
                                + (size_t)(k0 + kk) * 64 + (n & 63);
            *(float4*)&Ws[kk][wcol] = *(const float4*)wp;
        }
        __syncthreads();
        #pragma unroll
        for (int kk = 0; kk < 16; kk++) {
            float4 a0 = *(const float4*)&As[kk][ty << 2];
            float4 a1 = *(const float4*)&As[kk][64 + (ty << 2)];
            float4 b0 = *(const float4*)&Ws[kk][tx << 2];
            float4 b1 = *(const float4*)&Ws[kk][64 + (tx << 2)];
            float av[8] = {a0.x,a0.y,a0.z,a0.w,a1.x,a1.y,a1.z,a1.w};
            float bv[8] = {b0.x,b0.y,b0.z,b0.w,b1.x,b1.y,b1.z,b1.w};
            #pragma unroll
            for (int i = 0; i < 8; i++)
                #pragma unroll
                for (int j = 0; j < 8; j++)
                    acc[i][j] += av[i] * bv[j];
        }
        __syncthreads();
    }
    // epilogue
    #pragma unroll
    for (int i = 0; i < 8; i++) {
        int m = bm + ((i < 4) ? ((ty << 2) + i) : (64 + (ty << 2) + i - 4));
        #pragma unroll
        for (int half = 0; half < 2; half++) {
            int n = bn + half * 64 + (tx << 2);
            float v[4];
            #pragma unroll
            for (int j = 0; j < 4; j++) {
                float x = acc[i][half * 4 + j] + bias[n + j];
                if (GELU_) x = 0.5f * x * (1.f + erff(x * 0.70710678118654752f));
                v[j] = x;
            }
            if (RES) {
                float4 rr = *(const float4*)(Rp + (size_t)m * N + n);
                v[0] += rr.x; v[1] += rr.y; v[2] += rr.z; v[3] += rr.w;
            }
            float4 o; o.x = v[0]; o.y = v[1]; o.z = v[2]; o.w = v[3];
            *(float4*)(C + (size_t)m * N + n) = o;
        }
    }
}

// ---------------- flash attention (causal) ------------------------------------
// grid: (T/64, H, B); block 256.  Each thread: rows r and r+32, d-slice sub*8..+7
#define AST 68   // smem row stride (floats), keeps float4 alignment
__global__ __launch_bounds__(256) void attn_kernel(
    const float* __restrict__ Q, const float* __restrict__ K,
    const float* __restrict__ V, float* __restrict__ O)
{
    extern __shared__ float sm[];
    float* Qs = sm;
    float* Ks = sm + 64 * AST;
    float* Vs = sm + 2 * 64 * AST;
    float* Ps = sm + 3 * 64 * AST;

    int qt = blockIdx.x, h = blockIdx.y, b = blockIdx.z;
    int tid = threadIdx.x;
    int sub = tid & 7;       // d-slice index
    int r   = tid >> 3;      // 0..31 -> rows r and r+32

    const size_t base = ((size_t)(b * TT) << 10) + ((size_t)h << 6);

    // load Q tile [64][64]
    {
        int lr = tid >> 2, lc = (tid & 3) * 16;
        const float4* src = (const float4*)(Q + base + ((size_t)(qt * 64 + lr) << 10) + lc);
        float4* dst = (float4*)(Qs + lr * AST + lc);
        dst[0] = src[0]; dst[1] = src[1]; dst[2] = src[2]; dst[3] = src[3];
    }
    __syncthreads();

    float q0[8], q1[8];
    const float sc_qk = 0.125f;   // 1/sqrt(64)
    #pragma unroll
    for (int i = 0; i < 8; i++) {
        q0[i] = Qs[r * AST + sub * 8 + i] * sc_qk;
        q1[i] = Qs[(r + 32) * AST + sub * 8 + i] * sc_qk;
    }
    float m0 = -INFINITY, m1 = -INFINITY, l0 = 0.f, l1 = 0.f;
    float acc0[8], acc1[8];
    #pragma unroll
    for (int i = 0; i < 8; i++) { acc0[i] = 0.f; acc1[i] = 0.f; }
    int iq0 = qt * 64 + r, iq1 = iq0 + 32;

    for (int kt = 0; kt <= qt; kt++) {
        __syncthreads();   // prior-iteration consumers done before overwrite
        {
            int lr = tid >> 2, lc = (tid & 3) * 16;
            const float4* sk = (const float4*)(K + base + ((size_t)(kt * 64 + lr) << 10) + lc);
            const float4* sv = (const float4*)(V + base + ((size_t)(kt * 64 + lr) << 10) + lc);
            float4* dk = (float4*)(Ks + lr * AST + lc);
            float4* dv = (float4*)(Vs + lr * AST + lc);
            dk[0]=sk[0]; dk[1]=sk[1]; dk[2]=sk[2]; dk[3]=sk[3];
            dv[0]=sv[0]; dv[1]=sv[1]; dv[2]=sv[2]; dv[3]=sv[3];
        }
        __syncthreads();

        float mx0 = -INFINITY, mx1 = -INFINITY;
        bool diag = (kt == qt);
        #pragma unroll 4
        for (int j = 0; j < 64; j++) {
            const float4* kr = (const float4*)(Ks + j * AST + sub * 8);
            float4 ka = kr[0], kb = kr[1];
            float kk[8] = {ka.x,ka.y,ka.z,ka.w,kb.x,kb.y,kb.z,kb.w};
            float s0 = 0.f, s1 = 0.f;
            #pragma unroll
            for (int i = 0; i < 8; i++) { s0 += q0[i]*kk[i]; s1 += q1[i]*kk[i]; }
            #pragma unroll
            for (int o = 1; o < 8; o <<= 1) {
                s0 += __shfl_xor_sync(0xffffffffu, s0, o);
                s1 += __shfl_xor_sync(0xffffffffu, s1, o);
            }
            if (diag) {
                int jg = kt * 64 + j;
                if (jg > iq0) s0 = -INFINITY;
                if (jg > iq1) s1 = -INFINITY;
            }
            mx0 = fmaxf(mx0, s0); mx1 = fmaxf(mx1, s1);
            if (sub == (j & 7)) { Ps[r * AST + j] = s0; Ps[(r + 32) * AST + j] = s1; }
        }
        float nm0 = fmaxf(m0, mx0), nm1 = fmaxf(m1, mx1);
        float scl0 = expf(m0 - nm0), scl1 = expf(m1 - nm1);
        float ls0 = 0.f, ls1 = 0.f;
        #pragma unroll
        for (int jj = 0; jj < 8; jj++) {
            int j = jj * 8 + sub;
            float e0 = expf(Ps[r * AST + j] - nm0);
            float e1 = expf(Ps[(r + 32) * AST + j] - nm1);
            Ps[r * AST + j] = e0; Ps[(r + 32) * AST + j] = e1;
            ls0 += e0; ls1 += e1;
        }
        #pragma unroll
        for (int o = 1; o < 8; o <<= 1) {
            ls0 += __shfl_xor_sync(0xffffffffu, ls0, o);
            ls1 += __shfl_xor_sync(0xffffffffu, ls1, o);
        }
        l0 = l0 * scl0 + ls0; l1 = l1 * scl1 + ls1;
        #pragma unroll
        for (int i = 0; i < 8; i++) { acc0[i] *= scl0; acc1[i] *= scl1; }
        __syncwarp();
        #pragma unroll 4
        for (int j = 0; j < 64; j++) {
            float p0 = Ps[r * AST + j], p1 = Ps[(r + 32) * AST + j];
            const float4* vr = (const float4*)(Vs + j * AST + sub * 8);
            float4 va = vr[0], vb = vr[1];
            float vv[8] = {va.x,va.y,va.z,va.w,vb.x,vb.y,vb.z,vb.w};
            #pragma unroll
            for (int i = 0; i < 8; i++) { acc0[i] += p0*vv[i]; acc1[i] += p1*vv[i]; }
        }
        m0 = nm0; m1 = nm1;
    }

    float inv0 = 1.f / l0, inv1 = 1.f / l1;
    float* o0 = O + base + ((size_t)(qt * 64 + r) << 10) + sub * 8;
    float* o1 = O + base + ((size_t)(qt * 64 + r + 32) << 10) + sub * 8;
    float4 w0, w1;
    w0.x = acc0[0]*inv0; w0.y = acc0[1]*inv0; w0.z = acc0[2]*inv0; w0.w = acc0[3]*inv0;
    w1.x = acc0[4]*inv0; w1.y = acc0[5]*inv0; w1.z = acc0[6]*inv0; w1.w = acc0[7]*inv0;
    ((float4*)o0)[0] = w0; ((float4*)o0)[1] = w1;
    w0.x = acc1[0]*inv1; w0.y = acc1[1]*inv1; w0.z = acc1[2]*inv1; w0.w = acc1[3]*inv1;
    w1.x = acc1[4]*inv1; w1.y = acc1[5]*inv1; w1.z = acc1[6]*inv1; w1.w = acc1[7]*inv1;
    ((float4*)o1)[0] = w0; ((float4*)o1)[1] = w1;
}

// ---------------- launch ------------------------------------------------------
extern "C" void kernel_launch(void* const* d_in, const int* in_sizes, int n_in,
                              void* d_out, int out_size)
{
    const int*   ids   = (const int*)  d_in[0];
    const float* wte   = (const float*)d_in[1];
    const float* wpe   = (const float*)d_in[2];
    const float* wq    = (const float*)d_in[3];
    const float* wk    = (const float*)d_in[4];
    const float* wv    = (const float*)d_in[5];
    const float* bq    = (const float*)d_in[6];
    const float* bk    = (const float*)d_in[7];
    const float* bv    = (const float*)d_in[8];
    const float* wproj = (const float*)d_in[9];
    const float* bproj = (const float*)d_in[10];
    const float* ln1g  = (const float*)d_in[11];
    const float* ln1b  = (const float*)d_in[12];
    const float* ln2g  = (const float*)d_in[13];
    const float* ln2b  = (const float*)d_in[14];
    const float* wfc   = (const float*)d_in[15];
    const float* bfc   = (const float*)d_in[16];
    const float* wout  = (const float*)d_in[17];
    const float* bout  = (const float*)d_in[18];
    float* out = (float*)d_out;

    float *x, *h, *q, *k, *v, *o, *x2, *mb;
    cudaGetSymbolAddress((void**)&x,  g_x);
    cudaGetSymbolAddress((void**)&h,  g_h);
    cudaGetSymbolAddress((void**)&q,  g_q);
    cudaGetSymbolAddress((void**)&k,  g_k);
    cudaGetSymbolAddress((void**)&v,  g_v);
    cudaGetSymbolAddress((void**)&o,  g_o);
    cudaGetSymbolAddress((void**)&x2, g_x2);
    cudaGetSymbolAddress((void**)&mb, g_m);

    const int attn_smem = 4 * 64 * AST * 4;
    cudaFuncSetAttribute(attn_kernel, cudaFuncAttributeMaxDynamicSharedMemorySize, attn_smem);

    // 1. embed
    embed_kernel<<<(MM * EE / 4) / 256, 256>>>(ids, wte, wpe, x);
    // 2. ln1
    ln_kernel<<<MM, 256>>>(x, ln1g, ln1b, h);
    // 3. qkv projections  (W layout (H,E,D))
    dim3 g1(EE / 128, MM / 128);
    gemm_kernel<1, false, false><<<g1, 256>>>(h, wq, bq, nullptr, q, MM, EE, EE);
    gemm_kernel<1, false, false><<<g1, 256>>>(h, wk, bk, nullptr, k, MM, EE, EE);
    gemm_kernel<1, false, false><<<g1, 256>>>(h, wv, bv, nullptr, v, MM, EE, EE);
    // 4. causal flash attention
    attn_kernel<<<dim3(TT / 64, HH, BB), 256, attn_smem>>>(q, k, v, o);
    // 5. proj + residual  -> x2
    gemm_kernel<0, false, true><<<g1, 256>>>(o, wproj, bproj, x, x2, MM, EE, EE);
    // 6. ln2
    ln_kernel<<<MM, 256>>>(x2, ln2g, ln2b, h);
    // 7. fc + gelu -> m
    dim3 g2(FF / 128, MM / 128);
    gemm_kernel<0, true, false><<<g2, 256>>>(h, wfc, bfc, nullptr, mb, MM, FF, EE);
    // 8. out proj + residual -> d_out
    gemm_kernel<0, false, true><<<g1, 256>>>(mb, wout, bout, x2, out, MM, EE, FF);
}